// round 5
// baseline (speedup 1.0000x reference)
#include <cuda_runtime.h>
#include <cstdint>

#define BATCH 8
#define NN 4096
#define FF 128
#define UU 64
#define LOG2E 1.4426950408889634f
#define PSTR 72   // smem row stride (words) for Xs/Ps: 8g+2tig conflict-free

// ---------------- device scratch (no allocations allowed) -------------------
__device__ float  g_X[BATCH * NN * UU];    // X = H@W (fp32)
__device__ float  g_XT[BATCH * UU * NN];   // X^T per batch, tf32-rounded
__device__ float2 g_es2[BATCH * NN];       // (2^s~, 2^{0.2 s~})
__device__ float2 g_et2[BATCH * NN];       // (2^t~, 2^{0.2 t~})

// ---------------- helpers ---------------------------------------------------
__device__ __forceinline__ float ex2f(float x) {
    float r; asm("ex2.approx.f32 %0, %1;" : "=f"(r) : "f"(x)); return r;
}
__device__ __forceinline__ float tf32r(float x) {
    float y; asm("cvt.rna.tf32.f32 %0, %1;" : "=f"(y) : "f"(x)); return y;
}

// ---------------------------------------------------------------------------
// Kernel 1: X = H @ W (fp32, tiled). Also emits g_XT (transposed, tf32).
// ---------------------------------------------------------------------------
__global__ void __launch_bounds__(256) xgemm_kernel(const float* __restrict__ H,
                                                    const float* __restrict__ W) {
    __shared__ float Hst[64][68];
    __shared__ float Ws[64][64];
    const int row0 = blockIdx.x * 64;
    const int t = threadIdx.x;
    const int ty = t >> 4, tx = t & 15;

    float acc[4][4];
#pragma unroll
    for (int i = 0; i < 4; ++i)
#pragma unroll
        for (int j = 0; j < 4; ++j) acc[i][j] = 0.f;

    for (int kk = 0; kk < 2; ++kk) {
#pragma unroll
        for (int q = 0; q < 4; ++q) {
            int idx = t + q * 256;
            int r = idx >> 4, c4 = idx & 15;
            float4 v = *(const float4*)(H + (size_t)(row0 + r) * FF + kk * 64 + c4 * 4);
            Hst[c4 * 4 + 0][r] = v.x;
            Hst[c4 * 4 + 1][r] = v.y;
            Hst[c4 * 4 + 2][r] = v.z;
            Hst[c4 * 4 + 3][r] = v.w;
            float4 wv = *(const float4*)(W + (size_t)(kk * 64 + r) * UU + c4 * 4);
            *(float4*)&Ws[r][c4 * 4] = wv;
        }
        __syncthreads();
#pragma unroll
        for (int k = 0; k < 64; ++k) {
            float4 a = *(float4*)&Hst[k][ty * 4];
            float4 bv = *(float4*)&Ws[k][tx * 4];
            float ar[4] = {a.x, a.y, a.z, a.w};
            float br[4] = {bv.x, bv.y, bv.z, bv.w};
#pragma unroll
            for (int i = 0; i < 4; ++i)
#pragma unroll
                for (int j = 0; j < 4; ++j) acc[i][j] += ar[i] * br[j];
        }
        __syncthreads();
    }
    const int bb = row0 >> 12;          // batch
    const int n0 = row0 & (NN - 1);
#pragma unroll
    for (int i = 0; i < 4; ++i) {
        float4 v = make_float4(acc[i][0], acc[i][1], acc[i][2], acc[i][3]);
        *(float4*)(g_X + (size_t)(row0 + ty * 4 + i) * UU + tx * 4) = v;
    }
#pragma unroll
    for (int j = 0; j < 4; ++j) {
        float4 tv = make_float4(tf32r(acc[0][j]), tf32r(acc[1][j]),
                                tf32r(acc[2][j]), tf32r(acc[3][j]));
        *(float4*)(g_XT + ((size_t)bb * UU + tx * 4 + j) * NN + n0 + ty * 4) = tv;
    }
}

// ---------------------------------------------------------------------------
// Kernel 2: per-row exp factors. s~ = (X@a1)*log2e, t~ = (X@a2)*log2e
// ---------------------------------------------------------------------------
__global__ void __launch_bounds__(256) st_kernel(const float* __restrict__ a1,
                                                 const float* __restrict__ a2) {
    int gw = (blockIdx.x * blockDim.x + threadIdx.x) >> 5;
    int lane = threadIdx.x & 31;
    float x0 = g_X[(size_t)gw * UU + lane];
    float x1 = g_X[(size_t)gw * UU + 32 + lane];
    float sv = x0 * a1[lane] + x1 * a1[lane + 32];
    float tv = x0 * a2[lane] + x1 * a2[lane + 32];
#pragma unroll
    for (int o = 16; o; o >>= 1) {
        sv += __shfl_xor_sync(0xffffffffu, sv, o);
        tv += __shfl_xor_sync(0xffffffffu, tv, o);
    }
    if (lane == 0) {
        sv *= LOG2E; tv *= LOG2E;
        g_es2[gw] = make_float2(ex2f(sv), ex2f(0.2f * sv));
        g_et2[gw] = make_float2(ex2f(tv), ex2f(0.2f * tv));
    }
}

// ---------------------------------------------------------------------------
// Kernel 3: fused mask + unnormalized softmax + P@X via mma.sync tf32.
// Grid (32, 8). CTA = 128 thr (4 warps); warp w owns rows [32w, 32w+32),
// all 64 U cols. Loop 64 j-tiles of 64. acc[2][8] per lane (M=32, N=64).
// Paired-k layout: phys cols (kc*8+2t, +1) hold logical k = (kc*8+t, +4)
// => all fragment loads are LDS.64, conflict-free at row stride 72.
// ---------------------------------------------------------------------------
#define WXS 0                       // Xs: [64][72]
#define WPS (64 * PSTR)             // Ps: [4][32][72]
#define WZS (WPS + 4 * 32 * PSTR)   // Zs: [128]
#define WES (WZS + 128)             // Es2: [128] float2
#define SMEM_GAT ((WES + 256) * 4)

__global__ void __launch_bounds__(128, 3) gat_kernel(const float* __restrict__ A,
                                                     float* __restrict__ out) {
    extern __shared__ float sm[];
    float* Xs = sm + WXS;
    float* Ps = sm + WPS;
    float* Zs = sm + WZS;
    float2* Es2 = (float2*)(sm + WES);

    const int b = blockIdx.y;
    const int i0 = blockIdx.x * 128;
    const int tid = threadIdx.x;
    const int w = tid >> 5, lane = tid & 31;
    const int g = lane >> 2, tig = lane & 3;
    const int h = lane >> 4, c = lane & 15;
    const int wrow0 = i0 + w * 32;
    float* Psw = Ps + w * 32 * PSTR;

    // stage per-row exp factors into smem (one row per thread)
    Es2[tid] = g_es2[(size_t)b * NN + i0 + tid];

    float4 acc[2][8];
#pragma unroll
    for (int mh = 0; mh < 2; ++mh)
#pragma unroll
        for (int nb = 0; nb < 8; ++nb) acc[mh][nb] = make_float4(0.f, 0.f, 0.f, 0.f);
    float zp[16];
#pragma unroll
    for (int it = 0; it < 16; ++it) zp[it] = 0.f;

    const float* Abase = A + ((size_t)b * NN + wrow0 + 16 * h) * NN + 4 * c;
    const float2* etb = g_et2 + (size_t)b * NN + 4 * c;
    const float* XTb = g_XT + (size_t)b * UU * NN;
    const float2* Esw = Es2 + w * 32 + 16 * h;

    for (int jt = 0; jt < NN / 64; ++jt) {
        const int j0 = jt * 64;
        __syncthreads();  // previous MMA done reading Xs/Ps (also orders Es2 init)

        // --- X tile: straight coalesced copy from pre-transposed tf32 X ---
#pragma unroll
        for (int q = 0; q < 8; ++q) {
            int idx = tid + q * 128;
            int u = idx >> 4, c4 = idx & 15;
            float4 v = __ldg((const float4*)(XTb + (size_t)u * NN + j0 + c4 * 4));
            *(float4*)&Xs[u * PSTR + c4 * 4] = v;
        }

        // --- P stage: p = A * max(Es*Et, Es5*Et5); lane: 16 rows x 4 cols ---
        float4 et01 = *(const float4*)(etb + j0);      // (et[4c], et[4c+1])
        float4 et23 = *(const float4*)(etb + j0 + 2);  // (et[4c+2], et[4c+3])
        const float* Ap = Abase + j0;
#pragma unroll
        for (int it = 0; it < 16; ++it) {
            float4 m = __ldcs((const float4*)(Ap + (size_t)it * NN));
            float2 ef = Esw[it];
            float e0 = tf32r(m.x * fmaxf(ef.x * et01.x, ef.y * et01.y));
            float e1 = tf32r(m.y * fmaxf(ef.x * et01.z, ef.y * et01.w));
            float e2 = tf32r(m.z * fmaxf(ef.x * et23.x, ef.y * et23.y));
            float e3 = tf32r(m.w * fmaxf(ef.x * et23.z, ef.y * et23.w));
            zp[it] += (e0 + e1) + (e2 + e3);
            *(float4*)&Psw[(16 * h + it) * PSTR + 4 * c] = make_float4(e0, e1, e2, e3);
        }
        __syncthreads();

        // --- MMA: D[32x64] += P[32x64] @ X[64x64]^T, paired-k LDS.64 frags ---
#pragma unroll
        for (int kc = 0; kc < 8; ++kc) {
            const int off = kc * 8 + 2 * tig;
            float2 bv[8];
#pragma unroll
            for (int nb = 0; nb < 8; ++nb)
                bv[nb] = *(float2*)&Xs[(nb * 8 + g) * PSTR + off];
#pragma unroll
            for (int mh = 0; mh < 2; ++mh) {
                float2 a02 = *(float2*)&Psw[(16 * mh + g) * PSTR + off];
                float2 a13 = *(float2*)&Psw[(16 * mh + g + 8) * PSTR + off];
                uint32_t a0 = __float_as_uint(a02.x), a1 = __float_as_uint(a13.x);
                uint32_t a2v = __float_as_uint(a02.y), a3 = __float_as_uint(a13.y);
#pragma unroll
                for (int nb = 0; nb < 8; ++nb) {
                    asm volatile(
                        "mma.sync.aligned.m16n8k8.row.col.f32.tf32.tf32.f32 "
                        "{%0,%1,%2,%3}, {%4,%5,%6,%7}, {%8,%9}, {%0,%1,%2,%3};\n"
                        : "+f"(acc[mh][nb].x), "+f"(acc[mh][nb].y),
                          "+f"(acc[mh][nb].z), "+f"(acc[mh][nb].w)
                        : "r"(a0), "r"(a1), "r"(a2v), "r"(a3),
                          "r"(__float_as_uint(bv[nb].x)), "r"(__float_as_uint(bv[nb].y)));
                }
            }
        }
    }

    // --- Z reduction over the 16 column-lanes of each half-warp ---
#pragma unroll
    for (int it = 0; it < 16; ++it) {
        float v = zp[it];
#pragma unroll
        for (int o = 8; o; o >>= 1) v += __shfl_xor_sync(0xffffffffu, v, o);
        if (c == 0) Zs[w * 32 + 16 * h + it] = v;
    }
    __syncwarp();

    // --- epilogue: relu(D / Z) ---
    float* outb = out + ((size_t)b * NN + wrow0) * UU;
#pragma unroll
    for (int mh = 0; mh < 2; ++mh) {
        float inv0 = 1.0f / Zs[w * 32 + 16 * mh + g];
        float inv1 = 1.0f / Zs[w * 32 + 16 * mh + g + 8];
        float* o0 = outb + (size_t)(16 * mh + g) * UU;
        float* o1 = outb + (size_t)(16 * mh + g + 8) * UU;
#pragma unroll
        for (int nb = 0; nb < 8; ++nb) {
            int col = nb * 8 + tig * 2;
            *(float2*)(o0 + col) = make_float2(fmaxf(acc[mh][nb].x * inv0, 0.f),
                                               fmaxf(acc[mh][nb].y * inv0, 0.f));
            *(float2*)(o1 + col) = make_float2(fmaxf(acc[mh][nb].z * inv1, 0.f),
                                               fmaxf(acc[mh][nb].w * inv1, 0.f));
        }
    }
}

// ---------------------------------------------------------------------------
extern "C" void kernel_launch(void* const* d_in, const int* in_sizes, int n_in,
                              void* d_out, int out_size) {
    const float* H = (const float*)d_in[0];       // [8,4096,128]
    const float* Amask = (const float*)d_in[1];   // [8,4096,4096]
    const float* W = (const float*)d_in[2];       // [128,64]
    const float* a1 = (const float*)d_in[3];      // [64,1]
    const float* a2 = (const float*)d_in[4];      // [64,1]
    float* out = (float*)d_out;                   // [8,4096,64]

    cudaFuncSetAttribute(gat_kernel, cudaFuncAttributeMaxDynamicSharedMemorySize, SMEM_GAT);

    xgemm_kernel<<<(BATCH * NN) / 64, 256>>>(H, W);
    st_kernel<<<(BATCH * NN) / 8, 256>>>(a1, a2);
    gat_kernel<<<dim3(NN / 128, BATCH), 128, SMEM_GAT>>>(Amask, out);
}

// round 6
// speedup vs baseline: 1.1051x; 1.1051x over previous
#include <cuda_runtime.h>
#include <cstdint>

#define BATCH 8
#define NN 4096
#define FF 128
#define UU 64
#define LOG2E 1.4426950408889634f

// ---------------- device scratch (no allocations allowed) -------------------
__device__ float  g_X[BATCH * NN * UU];    // X = H@W (fp32)
__device__ float  g_XT[BATCH * UU * NN];   // X^T per batch, tf32-rounded
__device__ float2 g_es2[BATCH * NN];       // (2^s~, 2^{0.2 s~})
__device__ float2 g_et2[BATCH * NN];       // (2^t~, 2^{0.2 t~})

// ---------------- helpers ---------------------------------------------------
__device__ __forceinline__ float ex2f(float x) {
    float r; asm("ex2.approx.f32 %0, %1;" : "=f"(r) : "f"(x)); return r;
}
__device__ __forceinline__ float tf32r(float x) {
    float y; asm("cvt.rna.tf32.f32 %0, %1;" : "=f"(y) : "f"(x)); return y;
}

// ---------------------------------------------------------------------------
// Kernel 1: X = H @ W (fp32, tiled). Also emits g_XT (transposed, tf32).
// ---------------------------------------------------------------------------
__global__ void __launch_bounds__(256) xgemm_kernel(const float* __restrict__ H,
                                                    const float* __restrict__ W) {
    __shared__ float Hst[64][68];
    __shared__ float Ws[64][64];
    const int row0 = blockIdx.x * 64;
    const int t = threadIdx.x;
    const int ty = t >> 4, tx = t & 15;

    float acc[4][4];
#pragma unroll
    for (int i = 0; i < 4; ++i)
#pragma unroll
        for (int j = 0; j < 4; ++j) acc[i][j] = 0.f;

    for (int kk = 0; kk < 2; ++kk) {
#pragma unroll
        for (int q = 0; q < 4; ++q) {
            int idx = t + q * 256;
            int r = idx >> 4, c4 = idx & 15;
            float4 v = *(const float4*)(H + (size_t)(row0 + r) * FF + kk * 64 + c4 * 4);
            Hst[c4 * 4 + 0][r] = v.x;
            Hst[c4 * 4 + 1][r] = v.y;
            Hst[c4 * 4 + 2][r] = v.z;
            Hst[c4 * 4 + 3][r] = v.w;
            float4 wv = *(const float4*)(W + (size_t)(kk * 64 + r) * UU + c4 * 4);
            *(float4*)&Ws[r][c4 * 4] = wv;
        }
        __syncthreads();
#pragma unroll
        for (int k = 0; k < 64; ++k) {
            float4 a = *(float4*)&Hst[k][ty * 4];
            float4 bv = *(float4*)&Ws[k][tx * 4];
            float ar[4] = {a.x, a.y, a.z, a.w};
            float br[4] = {bv.x, bv.y, bv.z, bv.w};
#pragma unroll
            for (int i = 0; i < 4; ++i)
#pragma unroll
                for (int j = 0; j < 4; ++j) acc[i][j] += ar[i] * br[j];
        }
        __syncthreads();
    }
    const int bb = row0 >> 12;          // batch
    const int n0 = row0 & (NN - 1);
#pragma unroll
    for (int i = 0; i < 4; ++i) {
        float4 v = make_float4(acc[i][0], acc[i][1], acc[i][2], acc[i][3]);
        *(float4*)(g_X + (size_t)(row0 + ty * 4 + i) * UU + tx * 4) = v;
    }
#pragma unroll
    for (int j = 0; j < 4; ++j) {
        float4 tv = make_float4(tf32r(acc[0][j]), tf32r(acc[1][j]),
                                tf32r(acc[2][j]), tf32r(acc[3][j]));
        *(float4*)(g_XT + ((size_t)bb * UU + tx * 4 + j) * NN + n0 + ty * 4) = tv;
    }
}

// ---------------------------------------------------------------------------
// Kernel 2: per-row exp factors. s~ = (X@a1)*log2e, t~ = (X@a2)*log2e
// ---------------------------------------------------------------------------
__global__ void __launch_bounds__(256) st_kernel(const float* __restrict__ a1,
                                                 const float* __restrict__ a2) {
    int gw = (blockIdx.x * blockDim.x + threadIdx.x) >> 5;
    int lane = threadIdx.x & 31;
    float x0 = g_X[(size_t)gw * UU + lane];
    float x1 = g_X[(size_t)gw * UU + 32 + lane];
    float sv = x0 * a1[lane] + x1 * a1[lane + 32];
    float tv = x0 * a2[lane] + x1 * a2[lane + 32];
#pragma unroll
    for (int o = 16; o; o >>= 1) {
        sv += __shfl_xor_sync(0xffffffffu, sv, o);
        tv += __shfl_xor_sync(0xffffffffu, tv, o);
    }
    if (lane == 0) {
        sv *= LOG2E; tv *= LOG2E;
        g_es2[gw] = make_float2(ex2f(sv), ex2f(0.2f * sv));
        g_et2[gw] = make_float2(ex2f(tv), ex2f(0.2f * tv));
    }
}

// ---------------------------------------------------------------------------
// Kernel 3: fused mask + unnormalized softmax + P@X via mma.sync tf32.
// Grid (32, 8). CTA = 256 thr (8 warps); warp w owns rows [16w, 16w+16).
// Loop 64 j-tiles of 64. Lane: h = lane>>4, c = lane&15; handles rows
// (it + 8h), cols 4c..4c+3. Two barriers per tile; A loads front-batched.
// ---------------------------------------------------------------------------
#define WXS 0                        // Xs: [64][68]
#define WPS (64 * 68)                // Ps: [8][16][68]
#define WZS (WPS + 8 * 16 * 68)      // Zs: [128]
#define WES (WZS + 128)              // Es2: [128] float2
#define SMEM_GAT ((WES + 256) * 4)

__global__ void __launch_bounds__(256, 3) gat_kernel(const float* __restrict__ A,
                                                     float* __restrict__ out) {
    extern __shared__ float sm[];
    float* Xs = sm + WXS;
    float* Ps = sm + WPS;
    float* Zs = sm + WZS;
    float2* Es2 = (float2*)(sm + WES);

    const int b = blockIdx.y;
    const int i0 = blockIdx.x * 128;
    const int tid = threadIdx.x;
    const int w = tid >> 5, lane = tid & 31;
    const int g = lane >> 2, tig = lane & 3;
    const int h = lane >> 4, c = lane & 15;
    const int wrow0 = i0 + w * 16;
    float* Psw = Ps + w * 16 * 68;

    // stage per-row exp factors into smem (one row per thread; tid 0..127 used)
    if (tid < 128) Es2[tid] = g_es2[(size_t)b * NN + i0 + tid];

    float4 acc[8];
#pragma unroll
    for (int nb = 0; nb < 8; ++nb) acc[nb] = make_float4(0.f, 0.f, 0.f, 0.f);
    float zp[8];
#pragma unroll
    for (int it = 0; it < 8; ++it) zp[it] = 0.f;

    const float* Abase = A + ((size_t)b * NN + wrow0 + 8 * h) * NN + 4 * c;
    const float2* etb = g_et2 + (size_t)b * NN + 4 * c;
    const float* XTb = g_XT + (size_t)b * UU * NN;
    const float2* Esw = Es2 + w * 16 + 8 * h;

    for (int jt = 0; jt < NN / 64; ++jt) {
        const int j0 = jt * 64;
        __syncthreads();   // prev MMA done reading Xs/Ps (also orders Es2 init)

        // --- A loads first: 8 independent LDG.128 (front-batched MLP) ---
        const float* Ap = Abase + j0;
        float4 m0 = __ldcs((const float4*)(Ap + (size_t)0 * NN));
        float4 m1 = __ldcs((const float4*)(Ap + (size_t)1 * NN));
        float4 m2 = __ldcs((const float4*)(Ap + (size_t)2 * NN));
        float4 m3 = __ldcs((const float4*)(Ap + (size_t)3 * NN));
        float4 m4 = __ldcs((const float4*)(Ap + (size_t)4 * NN));
        float4 m5 = __ldcs((const float4*)(Ap + (size_t)5 * NN));
        float4 m6 = __ldcs((const float4*)(Ap + (size_t)6 * NN));
        float4 m7 = __ldcs((const float4*)(Ap + (size_t)7 * NN));

        // --- X tile: straight coalesced copy from pre-transposed tf32 X ---
#pragma unroll
        for (int q = 0; q < 4; ++q) {
            int idx = tid + q * 256;
            int u = idx >> 4, c4 = idx & 15;
            float4 v = __ldg((const float4*)(XTb + (size_t)u * NN + j0 + c4 * 4));
            *(float4*)&Xs[u * 68 + c4 * 4] = v;
        }

        // --- column factors for this lane's 4 columns ---
        float4 et01 = *(const float4*)(etb + j0);      // (et[4c], et[4c+1])
        float4 et23 = *(const float4*)(etb + j0 + 2);  // (et[4c+2], et[4c+3])

        // --- P stage: p = A * max(Es*Et, Es5*Et5) ---
        float4 mv[8] = {m0, m1, m2, m3, m4, m5, m6, m7};
#pragma unroll
        for (int it = 0; it < 8; ++it) {
            float4 m = mv[it];
            float2 ef = Esw[it];
            float e0 = tf32r(m.x * fmaxf(ef.x * et01.x, ef.y * et01.y));
            float e1 = tf32r(m.y * fmaxf(ef.x * et01.z, ef.y * et01.w));
            float e2 = tf32r(m.z * fmaxf(ef.x * et23.x, ef.y * et23.y));
            float e3 = tf32r(m.w * fmaxf(ef.x * et23.z, ef.y * et23.w));
            zp[it] += (e0 + e1) + (e2 + e3);
            *(float4*)&Psw[(it + 8 * h) * 68 + 4 * c] = make_float4(e0, e1, e2, e3);
        }
        __syncthreads();   // Xs + Ps ready for MMA

        // --- MMA: D[16x64] += P[16x64] @ X[64x64]^T  (8 kc x 8 nb) ---
#pragma unroll
        for (int kc = 0; kc < 8; ++kc) {
            const int jc = kc * 8 + tig;
            uint32_t a0 = __float_as_uint(Psw[g * 68 + jc]);
            uint32_t a1 = __float_as_uint(Psw[(g + 8) * 68 + jc]);
            uint32_t a2v = __float_as_uint(Psw[g * 68 + jc + 4]);
            uint32_t a3 = __float_as_uint(Psw[(g + 8) * 68 + jc + 4]);
#pragma unroll
            for (int nb = 0; nb < 8; ++nb) {
                uint32_t b0 = __float_as_uint(Xs[(nb * 8 + g) * 68 + jc]);
                uint32_t b1 = __float_as_uint(Xs[(nb * 8 + g) * 68 + jc + 4]);
                asm volatile(
                    "mma.sync.aligned.m16n8k8.row.col.f32.tf32.tf32.f32 "
                    "{%0,%1,%2,%3}, {%4,%5,%6,%7}, {%8,%9}, {%0,%1,%2,%3};\n"
                    : "+f"(acc[nb].x), "+f"(acc[nb].y), "+f"(acc[nb].z), "+f"(acc[nb].w)
                    : "r"(a0), "r"(a1), "r"(a2v), "r"(a3), "r"(b0), "r"(b1));
            }
        }
    }

    // --- Z reduction: rows it (lanes 0-15) and it+8 (lanes 16-31) ---
#pragma unroll
    for (int it = 0; it < 8; ++it) {
        float v = zp[it];
#pragma unroll
        for (int o = 8; o; o >>= 1) v += __shfl_xor_sync(0xffffffffu, v, o);
        if (c == 0) Zs[w * 16 + 8 * h + it] = v;   // lane 0 and lane 16 write
    }
    __syncwarp();

    // --- epilogue: relu(D / Z) ---
    float inv0 = 1.0f / Zs[w * 16 + g];
    float inv1 = 1.0f / Zs[w * 16 + g + 8];
    float* outb = out + ((size_t)b * NN + wrow0) * UU;
#pragma unroll
    for (int nb = 0; nb < 8; ++nb) {
        int col = nb * 8 + tig * 2;
        float2 v0 = make_float2(fmaxf(acc[nb].x * inv0, 0.f), fmaxf(acc[nb].y * inv0, 0.f));
        float2 v1 = make_float2(fmaxf(acc[nb].z * inv1, 0.f), fmaxf(acc[nb].w * inv1, 0.f));
        *(float2*)(outb + (size_t)g * UU + col) = v0;
        *(float2*)(outb + (size_t)(g + 8) * UU + col) = v1;
    }
}

// ---------------------------------------------------------------------------
extern "C" void kernel_launch(void* const* d_in, const int* in_sizes, int n_in,
                              void* d_out, int out_size) {
    const float* H = (const float*)d_in[0];       // [8,4096,128]
    const float* Amask = (const float*)d_in[1];   // [8,4096,4096]
    const float* W = (const float*)d_in[2];       // [128,64]
    const float* a1 = (const float*)d_in[3];      // [64,1]
    const float* a2 = (const float*)d_in[4];      // [64,1]
    float* out = (float*)d_out;                   // [8,4096,64]

    cudaFuncSetAttribute(gat_kernel, cudaFuncAttributeMaxDynamicSharedMemorySize, SMEM_GAT);

    xgemm_kernel<<<(BATCH * NN) / 64, 256>>>(H, W);
    st_kernel<<<(BATCH * NN) / 8, 256>>>(a1, a2);
    gat_kernel<<<dim3(NN / 128, BATCH), 256, SMEM_GAT>>>(Amask, out);
}

// round 7
// speedup vs baseline: 2.1072x; 1.9067x over previous
#include <cuda_runtime.h>
#include <cstdint>

#define BATCH 8
#define NN 4096
#define FF 128
#define UU 64
#define LOG2E 1.4426950408889634f

// ---------------- device scratch (no allocations allowed) -------------------
__device__ float  g_X[BATCH * NN * UU];    // X = H@W (fp32)
__device__ float  g_XT[BATCH * UU * NN];   // X^T per batch, tf32-rounded
__device__ float2 g_es2[BATCH * NN];       // (2^s~, 2^{0.2 s~})
__device__ float2 g_et2[BATCH * NN];       // (2^t~, 2^{0.2 t~})

// ---------------- helpers ---------------------------------------------------
__device__ __forceinline__ float ex2f(float x) {
    float r; asm("ex2.approx.f32 %0, %1;" : "=f"(r) : "f"(x)); return r;
}
__device__ __forceinline__ float tf32r(float x) {
    float y; asm("cvt.rna.tf32.f32 %0, %1;" : "=f"(y) : "f"(x)); return y;
}

// ---------------------------------------------------------------------------
// Kernel 1: X = H @ W (fp32, tiled). Also emits g_XT (transposed, tf32).
// ---------------------------------------------------------------------------
__global__ void __launch_bounds__(256) xgemm_kernel(const float* __restrict__ H,
                                                    const float* __restrict__ W) {
    __shared__ float Hst[64][68];
    __shared__ float Ws[64][64];
    const int row0 = blockIdx.x * 64;
    const int t = threadIdx.x;
    const int ty = t >> 4, tx = t & 15;

    float acc[4][4];
#pragma unroll
    for (int i = 0; i < 4; ++i)
#pragma unroll
        for (int j = 0; j < 4; ++j) acc[i][j] = 0.f;

    for (int kk = 0; kk < 2; ++kk) {
#pragma unroll
        for (int q = 0; q < 4; ++q) {
            int idx = t + q * 256;
            int r = idx >> 4, c4 = idx & 15;
            float4 v = *(const float4*)(H + (size_t)(row0 + r) * FF + kk * 64 + c4 * 4);
            Hst[c4 * 4 + 0][r] = v.x;
            Hst[c4 * 4 + 1][r] = v.y;
            Hst[c4 * 4 + 2][r] = v.z;
            Hst[c4 * 4 + 3][r] = v.w;
            float4 wv = *(const float4*)(W + (size_t)(kk * 64 + r) * UU + c4 * 4);
            *(float4*)&Ws[r][c4 * 4] = wv;
        }
        __syncthreads();
#pragma unroll
        for (int k = 0; k < 64; ++k) {
            float4 a = *(float4*)&Hst[k][ty * 4];
            float4 bv = *(float4*)&Ws[k][tx * 4];
            float ar[4] = {a.x, a.y, a.z, a.w};
            float br[4] = {bv.x, bv.y, bv.z, bv.w};
#pragma unroll
            for (int i = 0; i < 4; ++i)
#pragma unroll
                for (int j = 0; j < 4; ++j) acc[i][j] += ar[i] * br[j];
        }
        __syncthreads();
    }
    const int bb = row0 >> 12;          // batch
    const int n0 = row0 & (NN - 1);
#pragma unroll
    for (int i = 0; i < 4; ++i) {
        float4 v = make_float4(acc[i][0], acc[i][1], acc[i][2], acc[i][3]);
        *(float4*)(g_X + (size_t)(row0 + ty * 4 + i) * UU + tx * 4) = v;
    }
#pragma unroll
    for (int j = 0; j < 4; ++j) {
        float4 tv = make_float4(tf32r(acc[0][j]), tf32r(acc[1][j]),
                                tf32r(acc[2][j]), tf32r(acc[3][j]));
        *(float4*)(g_XT + ((size_t)bb * UU + tx * 4 + j) * NN + n0 + ty * 4) = tv;
    }
}

// ---------------------------------------------------------------------------
// Kernel 2: per-row exp factors. s~ = (X@a1)*log2e, t~ = (X@a2)*log2e
// ---------------------------------------------------------------------------
__global__ void __launch_bounds__(256) st_kernel(const float* __restrict__ a1,
                                                 const float* __restrict__ a2) {
    int gw = (blockIdx.x * blockDim.x + threadIdx.x) >> 5;
    int lane = threadIdx.x & 31;
    float x0 = g_X[(size_t)gw * UU + lane];
    float x1 = g_X[(size_t)gw * UU + 32 + lane];
    float sv = x0 * a1[lane] + x1 * a1[lane + 32];
    float tv = x0 * a2[lane] + x1 * a2[lane + 32];
#pragma unroll
    for (int o = 16; o; o >>= 1) {
        sv += __shfl_xor_sync(0xffffffffu, sv, o);
        tv += __shfl_xor_sync(0xffffffffu, tv, o);
    }
    if (lane == 0) {
        sv *= LOG2E; tv *= LOG2E;
        g_es2[gw] = make_float2(ex2f(sv), ex2f(0.2f * sv));
        g_et2[gw] = make_float2(ex2f(tv), ex2f(0.2f * tv));
    }
}

// ---------------------------------------------------------------------------
// Kernel 3: fused mask + unnormalized softmax + P@X via mma.sync tf32.
// Grid (32, 8). CTA = 256 thr (8 warps); warp w owns rows [16w, 16w+16).
// Loop 64 j-tiles of 64. Lane: h = lane>>4, c = lane&15; handles rows
// (it + 8h), cols 4c..4c+3.
// Pipeline: A for tile jt+1 is loaded into the SAME registers right after
// the P stage consumes tile jt's values -> loads drain during MMA + X-copy
// (full DRAM latency of cover) at zero extra peak register cost.
// ---------------------------------------------------------------------------
#define WXS 0                        // Xs: [64][68]
#define WPS (64 * 68)                // Ps: [8][16][68]
#define WZS (WPS + 8 * 16 * 68)      // Zs: [128]
#define WES (WZS + 128)              // Es2: [128] float2
#define SMEM_GAT ((WES + 256) * 4)

__global__ void __launch_bounds__(256, 2) gat_kernel(const float* __restrict__ A,
                                                     float* __restrict__ out) {
    extern __shared__ float sm[];
    float* Xs = sm + WXS;
    float* Ps = sm + WPS;
    float* Zs = sm + WZS;
    float2* Es2 = (float2*)(sm + WES);

    const int b = blockIdx.y;
    const int i0 = blockIdx.x * 128;
    const int tid = threadIdx.x;
    const int w = tid >> 5, lane = tid & 31;
    const int g = lane >> 2, tig = lane & 3;
    const int h = lane >> 4, c = lane & 15;
    const int wrow0 = i0 + w * 16;
    float* Psw = Ps + w * 16 * 68;

    // stage per-row exp factors into smem (rows i0..i0+127)
    if (tid < 128) Es2[tid] = g_es2[(size_t)b * NN + i0 + tid];

    float4 acc[8];
#pragma unroll
    for (int nb = 0; nb < 8; ++nb) acc[nb] = make_float4(0.f, 0.f, 0.f, 0.f);
    float zp[8];
#pragma unroll
    for (int it = 0; it < 8; ++it) zp[it] = 0.f;

    const float* Abase = A + ((size_t)b * NN + wrow0 + 8 * h) * NN + 4 * c;
    const float2* etb = g_et2 + (size_t)b * NN + 4 * c;
    const float* XTb = g_XT + (size_t)b * UU * NN;
    const float2* Esw = Es2 + w * 16 + 8 * h;

    // prologue: A loads for tile 0
    float4 mv[8];
#pragma unroll
    for (int it = 0; it < 8; ++it)
        mv[it] = __ldcs((const float4*)(Abase + (size_t)it * NN));

    for (int jt = 0; jt < NN / 64; ++jt) {
        const int j0 = jt * 64;
        __syncthreads();   // prev MMA done reading Xs/Ps (also orders Es2 init)

        // --- X tile: straight coalesced copy from pre-transposed tf32 X ---
#pragma unroll
        for (int q = 0; q < 4; ++q) {
            int idx = tid + q * 256;
            int u = idx >> 4, c4 = idx & 15;
            float4 v = __ldg((const float4*)(XTb + (size_t)u * NN + j0 + c4 * 4));
            *(float4*)&Xs[u * 68 + c4 * 4] = v;
        }

        // --- column factors for this lane's 4 columns ---
        float4 et01 = *(const float4*)(etb + j0);      // (et[4c], et[4c+1])
        float4 et23 = *(const float4*)(etb + j0 + 2);  // (et[4c+2], et[4c+3])

        // --- P stage: p = A * max(Es*Et, Es5*Et5), consuming mv (tile jt) ---
#pragma unroll
        for (int it = 0; it < 8; ++it) {
            float4 m = mv[it];
            float2 ef = Esw[it];
            float e0 = tf32r(m.x * fmaxf(ef.x * et01.x, ef.y * et01.y));
            float e1 = tf32r(m.y * fmaxf(ef.x * et01.z, ef.y * et01.w));
            float e2 = tf32r(m.z * fmaxf(ef.x * et23.x, ef.y * et23.y));
            float e3 = tf32r(m.w * fmaxf(ef.x * et23.z, ef.y * et23.w));
            zp[it] += (e0 + e1) + (e2 + e3);
            *(float4*)&Psw[(it + 8 * h) * 68 + 4 * c] = make_float4(e0, e1, e2, e3);
        }

        // --- prefetch A for tile jt+1 into the now-dead mv registers ---
        {
            const float* Apn = Abase + (size_t)(((jt + 1) & 63) * 64);
#pragma unroll
            for (int it = 0; it < 8; ++it)
                mv[it] = __ldcs((const float4*)(Apn + (size_t)it * NN));
        }
        __syncthreads();   // Xs + Ps ready for MMA

        // --- MMA: D[16x64] += P[16x64] @ X[64x64]^T  (8 kc x 8 nb) ---
#pragma unroll
        for (int kc = 0; kc < 8; ++kc) {
            const int jc = kc * 8 + tig;
            uint32_t a0 = __float_as_uint(Psw[g * 68 + jc]);
            uint32_t a1 = __float_as_uint(Psw[(g + 8) * 68 + jc]);
            uint32_t a2v = __float_as_uint(Psw[g * 68 + jc + 4]);
            uint32_t a3 = __float_as_uint(Psw[(g + 8) * 68 + jc + 4]);
#pragma unroll
            for (int nb = 0; nb < 8; ++nb) {
                uint32_t b0 = __float_as_uint(Xs[(nb * 8 + g) * 68 + jc]);
                uint32_t b1 = __float_as_uint(Xs[(nb * 8 + g) * 68 + jc + 4]);
                asm volatile(
                    "mma.sync.aligned.m16n8k8.row.col.f32.tf32.tf32.f32 "
                    "{%0,%1,%2,%3}, {%4,%5,%6,%7}, {%8,%9}, {%0,%1,%2,%3};\n"
                    : "+f"(acc[nb].x), "+f"(acc[nb].y), "+f"(acc[nb].z), "+f"(acc[nb].w)
                    : "r"(a0), "r"(a1), "r"(a2v), "r"(a3), "r"(b0), "r"(b1));
            }
        }
    }

    // --- Z reduction: rows it (lanes 0-15) and it+8 (lanes 16-31) ---
#pragma unroll
    for (int it = 0; it < 8; ++it) {
        float v = zp[it];
#pragma unroll
        for (int o = 8; o; o >>= 1) v += __shfl_xor_sync(0xffffffffu, v, o);
        if (c == 0) Zs[w * 16 + 8 * h + it] = v;   // lane 0 and lane 16 write
    }
    __syncwarp();

    // --- epilogue: relu(D / Z) ---
    float inv0 = 1.0f / Zs[w * 16 + g];
    float inv1 = 1.0f / Zs[w * 16 + g + 8];
    float* outb = out + ((size_t)b * NN + wrow0) * UU;
#pragma unroll
    for (int nb = 0; nb < 8; ++nb) {
        int col = nb * 8 + tig * 2;
        float2 v0 = make_float2(fmaxf(acc[nb].x * inv0, 0.f), fmaxf(acc[nb].y * inv0, 0.f));
        float2 v1 = make_float2(fmaxf(acc[nb].z * inv1, 0.f), fmaxf(acc[nb].w * inv1, 0.f));
        *(float2*)(outb + (size_t)g * UU + col) = v0;
        *(float2*)(outb + (size_t)(g + 8) * UU + col) = v1;
    }
}

// ---------------------------------------------------------------------------
extern "C" void kernel_launch(void* const* d_in, const int* in_sizes, int n_in,
                              void* d_out, int out_size) {
    const float* H = (const float*)d_in[0];       // [8,4096,128]
    const float* Amask = (const float*)d_in[1];   // [8,4096,4096]
    const float* W = (const float*)d_in[2];       // [128,64]
    const float* a1 = (const float*)d_in[3];      // [64,1]
    const float* a2 = (const float*)d_in[4];      // [64,1]
    float* out = (float*)d_out;                   // [8,4096,64]

    cudaFuncSetAttribute(gat_kernel, cudaFuncAttributeMaxDynamicSharedMemorySize, SMEM_GAT);

    xgemm_kernel<<<(BATCH * NN) / 64, 256>>>(H, W);
    st_kernel<<<(BATCH * NN) / 8, 256>>>(a1, a2);
    gat_kernel<<<dim3(NN / 128, BATCH), 256, SMEM_GAT>>>(Amask, out);
}

// round 10
// speedup vs baseline: 2.9846x; 1.4164x over previous
#include <cuda_runtime.h>
#include <cuda_fp16.h>
#include <cstdint>

#define BATCH 8
#define NN 4096
#define FF 128
#define UU 64
#define LOG2E 1.4426950408889634f
#define XSTR 36   // Xs row stride in half2 words (conflict-free frag reads)
#define PSTR 36   // Ps row stride in half2 words

// ---------------- device scratch (no allocations allowed) -------------------
__device__ float   g_X[BATCH * NN * UU];     // X = H@W (fp32)
__device__ __half  g_XTh[BATCH * UU * NN];   // X^T per batch, fp16
__device__ float2  g_es2[BATCH * NN];        // (2^s~, 2^{0.2 s~})
__device__ float2  g_et2[BATCH * NN];        // (2^t~, 2^{0.2 t~})

// ---------------- helpers ---------------------------------------------------
__device__ __forceinline__ float ex2f(float x) {
    float r; asm("ex2.approx.f32 %0, %1;" : "=f"(r) : "f"(x)); return r;
}

// ---------------------------------------------------------------------------
// Kernel 1: X = H @ W (fp32, tiled). Emits g_X (fp32) and g_XTh (fp16, T).
// ---------------------------------------------------------------------------
__global__ void __launch_bounds__(256) xgemm_kernel(const float* __restrict__ H,
                                                    const float* __restrict__ W) {
    __shared__ float Hst[64][68];
    __shared__ float Ws[64][64];
    const int row0 = blockIdx.x * 64;
    const int t = threadIdx.x;
    const int ty = t >> 4, tx = t & 15;

    float acc[4][4];
#pragma unroll
    for (int i = 0; i < 4; ++i)
#pragma unroll
        for (int j = 0; j < 4; ++j) acc[i][j] = 0.f;

    for (int kk = 0; kk < 2; ++kk) {
#pragma unroll
        for (int q = 0; q < 4; ++q) {
            int idx = t + q * 256;
            int r = idx >> 4, c4 = idx & 15;
            float4 v = *(const float4*)(H + (size_t)(row0 + r) * FF + kk * 64 + c4 * 4);
            Hst[c4 * 4 + 0][r] = v.x;
            Hst[c4 * 4 + 1][r] = v.y;
            Hst[c4 * 4 + 2][r] = v.z;
            Hst[c4 * 4 + 3][r] = v.w;
            float4 wv = *(const float4*)(W + (size_t)(kk * 64 + r) * UU + c4 * 4);
            *(float4*)&Ws[r][c4 * 4] = wv;
        }
        __syncthreads();
#pragma unroll
        for (int k = 0; k < 64; ++k) {
            float4 a = *(float4*)&Hst[k][ty * 4];
            float4 bv = *(float4*)&Ws[k][tx * 4];
            float ar[4] = {a.x, a.y, a.z, a.w};
            float br[4] = {bv.x, bv.y, bv.z, bv.w};
#pragma unroll
            for (int i = 0; i < 4; ++i)
#pragma unroll
                for (int j = 0; j < 4; ++j) acc[i][j] += ar[i] * br[j];
        }
        __syncthreads();
    }
    const int bb = row0 >> 12;          // batch
    const int n0 = row0 & (NN - 1);
#pragma unroll
    for (int i = 0; i < 4; ++i) {
        float4 v = make_float4(acc[i][0], acc[i][1], acc[i][2], acc[i][3]);
        *(float4*)(g_X + (size_t)(row0 + ty * 4 + i) * UU + tx * 4) = v;
    }
    // transposed fp16: XT[u][n], 4 consecutive n per store (8 B)
#pragma unroll
    for (int j = 0; j < 4; ++j) {
        __half2 h01 = __floats2half2_rn(acc[0][j], acc[1][j]);
        __half2 h23 = __floats2half2_rn(acc[2][j], acc[3][j]);
        uint2 pv = make_uint2(*(uint32_t*)&h01, *(uint32_t*)&h23);
        *(uint2*)(g_XTh + ((size_t)bb * UU + tx * 4 + j) * NN + n0 + ty * 4) = pv;
    }
}

// ---------------------------------------------------------------------------
// Kernel 2: per-row exp factors. s~ = (X@a1)*log2e, t~ = (X@a2)*log2e
// ---------------------------------------------------------------------------
__global__ void __launch_bounds__(256) st_kernel(const float* __restrict__ a1,
                                                 const float* __restrict__ a2) {
    int gw = (blockIdx.x * blockDim.x + threadIdx.x) >> 5;
    int lane = threadIdx.x & 31;
    float x0 = g_X[(size_t)gw * UU + lane];
    float x1 = g_X[(size_t)gw * UU + 32 + lane];
    float sv = x0 * a1[lane] + x1 * a1[lane + 32];
    float tv = x0 * a2[lane] + x1 * a2[lane + 32];
#pragma unroll
    for (int o = 16; o; o >>= 1) {
        sv += __shfl_xor_sync(0xffffffffu, sv, o);
        tv += __shfl_xor_sync(0xffffffffu, tv, o);
    }
    if (lane == 0) {
        sv *= LOG2E; tv *= LOG2E;
        g_es2[gw] = make_float2(ex2f(sv), ex2f(0.2f * sv));
        g_et2[gw] = make_float2(ex2f(tv), ex2f(0.2f * tv));
    }
}

// ---------------------------------------------------------------------------
// Kernel 3: fused mask + unnormalized softmax + P@X via mma.sync f16 (k16).
// Grid (32, 8). CTA = 256 thr (8 warps); warp w owns rows [16w, 16w+16).
// Loop 64 j-tiles of 64. P and X operands in half2 smem, fp32 accum + Z.
// A-prefetch for tile jt+1 reuses mv registers (drains during MMA).
// ---------------------------------------------------------------------------
#define WXS 0                            // Xs: [64][XSTR] half2 words
#define WPS (64 * XSTR)                  // Ps: [128][PSTR] half2 words
#define WZS (WPS + 128 * PSTR)           // Zs: [128] float
#define WES (WZS + 128)                  // Es2: [128] float2
#define SMEM_GAT ((WES + 256) * 4)

__global__ void __launch_bounds__(256, 2) gat_kernel(const float* __restrict__ A,
                                                     float* __restrict__ out) {
    extern __shared__ float sm[];
    uint32_t* Xs = (uint32_t*)(sm + WXS);   // half2 words
    uint32_t* Ps = (uint32_t*)(sm + WPS);   // half2 words
    float* Zs = sm + WZS;
    float2* Es2 = (float2*)(sm + WES);

    const int b = blockIdx.y;
    const int i0 = blockIdx.x * 128;
    const int tid = threadIdx.x;
    const int w = tid >> 5, lane = tid & 31;
    const int g = lane >> 2, tig = lane & 3;
    const int h = lane >> 4, c = lane & 15;
    const int wrow0 = i0 + w * 16;

    // stage per-row exp factors into smem (rows i0..i0+127)
    if (tid < 128) Es2[tid] = g_es2[(size_t)b * NN + i0 + tid];

    float4 acc[8];
#pragma unroll
    for (int nb = 0; nb < 8; ++nb) acc[nb] = make_float4(0.f, 0.f, 0.f, 0.f);
    float zp[8];
#pragma unroll
    for (int it = 0; it < 8; ++it) zp[it] = 0.f;

    const float* Abase = A + ((size_t)b * NN + wrow0 + 8 * h) * NN + 4 * c;
    const float2* etb = g_et2 + (size_t)b * NN + 4 * c;
    const __half* XTb = g_XTh + (size_t)b * UU * NN;
    const float2* Esw = Es2 + w * 16 + 8 * h;

    // prologue: A loads for tile 0
    float4 mv[8];
#pragma unroll
    for (int it = 0; it < 8; ++it)
        mv[it] = __ldcs((const float4*)(Abase + (size_t)it * NN));

    for (int jt = 0; jt < NN / 64; ++jt) {
        const int j0 = jt * 64;
        __syncthreads();   // prev MMA done reading Xs/Ps (also orders Es2 init)

        // --- X tile: coalesced fp16 copy; Xs[u][kw] = (X[j0+2kw][u], +1) ---
#pragma unroll
        for (int q = 0; q < 2; ++q) {
            int idx = tid + q * 256;
            int u = idx >> 3, ch = idx & 7;     // 8 chunks of 8 halves per row
            uint4 v = *(const uint4*)(XTb + (size_t)u * NN + j0 + ch * 8);
            *(uint4*)&Xs[u * XSTR + ch * 4] = v;
        }

        // --- column factors for this lane's 4 columns ---
        float4 et01 = *(const float4*)(etb + j0);      // (et[4c], et[4c+1])
        float4 et23 = *(const float4*)(etb + j0 + 2);  // (et[4c+2], et[4c+3])

        // --- P stage: p = A * max(Es*Et, Es5*Et5), packed to half2 ---
#pragma unroll
        for (int it = 0; it < 8; ++it) {
            float4 m = mv[it];
            float2 ef = Esw[it];
            float e0 = m.x * fmaxf(ef.x * et01.x, ef.y * et01.y);
            float e1 = m.y * fmaxf(ef.x * et01.z, ef.y * et01.w);
            float e2 = m.z * fmaxf(ef.x * et23.x, ef.y * et23.y);
            float e3 = m.w * fmaxf(ef.x * et23.z, ef.y * et23.w);
            zp[it] += (e0 + e1) + (e2 + e3);
            __half2 p01 = __floats2half2_rn(e0, e1);
            __half2 p23 = __floats2half2_rn(e2, e3);
            uint2 pw = make_uint2(*(uint32_t*)&p01, *(uint32_t*)&p23);
            *(uint2*)&Ps[(it + 8 * h + w * 16) * PSTR + 2 * c] = pw;
        }

        // --- prefetch A for tile jt+1 into the now-dead mv registers ---
        {
            const float* Apn = Abase + (size_t)(((jt + 1) & 63) * 64);
#pragma unroll
            for (int it = 0; it < 8; ++it)
                mv[it] = __ldcs((const float4*)(Apn + (size_t)it * NN));
        }
        __syncthreads();   // Xs + Ps ready for MMA

        // --- MMA: D[16x64] += P[16x64] @ X[64x64]^T  (4 kc x 8 nb, f16 k16) ---
        const uint32_t* Pw = Ps + (w * 16) * PSTR;
#pragma unroll
        for (int kc = 0; kc < 4; ++kc) {
            const int kw = kc * 8 + tig;
            uint32_t a0 = Pw[g * PSTR + kw];
            uint32_t a1 = Pw[(g + 8) * PSTR + kw];
            uint32_t a2v = Pw[g * PSTR + kw + 4];
            uint32_t a3 = Pw[(g + 8) * PSTR + kw + 4];
#pragma unroll
            for (int nb = 0; nb < 8; ++nb) {
                uint32_t b0 = Xs[(nb * 8 + g) * XSTR + kw];
                uint32_t b1 = Xs[(nb * 8 + g) * XSTR + kw + 4];
                asm volatile(
                    "mma.sync.aligned.m16n8k16.row.col.f32.f16.f16.f32 "
                    "{%0,%1,%2,%3}, {%4,%5,%6,%7}, {%8,%9}, {%0,%1,%2,%3};\n"
                    : "+f"(acc[nb].x), "+f"(acc[nb].y), "+f"(acc[nb].z), "+f"(acc[nb].w)
                    : "r"(a0), "r"(a1), "r"(a2v), "r"(a3), "r"(b0), "r"(b1));
            }
        }
    }

    // --- Z reduction: rows it (lanes 0-15) and it+8 (lanes 16-31) ---
#pragma unroll
    for (int it = 0; it < 8; ++it) {
        float v = zp[it];
#pragma unroll
        for (int o = 8; o; o >>= 1) v += __shfl_xor_sync(0xffffffffu, v, o);
        if (c == 0) Zs[w * 16 + 8 * h + it] = v;   // lane 0 and lane 16 write
    }
    __syncwarp();

    // --- epilogue: relu(D / Z) ---
    float inv0 = 1.0f / Zs[w * 16 + g];
    float inv1 = 1.0f / Zs[w * 16 + g + 8];
    float* outb = out + ((size_t)b * NN + wrow0) * UU;
#pragma unroll
    for (int nb = 0; nb < 8; ++nb) {
        int col = nb * 8 + tig * 2;
        float2 v0 = make_float2(fmaxf(acc[nb].x * inv0, 0.f), fmaxf(acc[nb].y * inv0, 0.f));
        float2 v1 = make_float2(fmaxf(acc[nb].z * inv1, 0.f), fmaxf(acc[nb].w * inv1, 0.f));
        *(float2*)(outb + (size_t)g * UU + col) = v0;
        *(float2*)(outb + (size_t)(g + 8) * UU + col) = v1;
    }
}

// ---------------------------------------------------------------------------
extern "C" void kernel_launch(void* const* d_in, const int* in_sizes, int n_in,
                              void* d_out, int out_size) {
    const float* H = (const float*)d_in[0];       // [8,4096,128]
    const float* Amask = (const float*)d_in[1];   // [8,4096,4096]
    const float* W = (const float*)d_in[2];       // [128,64]
    const float* a1 = (const float*)d_in[3];      // [64,1]
    const float* a2 = (const float*)d_in[4];      // [64,1]
    float* out = (float*)d_out;                   // [8,4096,64]

    cudaFuncSetAttribute(gat_kernel, cudaFuncAttributeMaxDynamicSharedMemorySize, SMEM_GAT);

    xgemm_kernel<<<(BATCH * NN) / 64, 256>>>(H, W);
    st_kernel<<<(BATCH * NN) / 8, 256>>>(a1, a2);
    gat_kernel<<<dim3(NN / 128, BATCH), 256, SMEM_GAT>>>(Amask, out);
}

// round 11
// speedup vs baseline: 3.3139x; 1.1103x over previous
#include <cuda_runtime.h>
#include <cuda_fp16.h>
#include <cstdint>

#define BATCH 8
#define NN 4096
#define FF 128
#define UU 64
#define LOG2E 1.4426950408889634f
#define XSTR 36   // Xs row stride in half2 words (ldsm rows land on banks 4r..4r+3)
#define PSTR 36   // Ps row stride in half2 words

// ---------------- device scratch (no allocations allowed) -------------------
__device__ float   g_X[BATCH * NN * UU];     // X = H@W (fp32)
__device__ __half  g_XTh[BATCH * UU * NN];   // X^T per batch, fp16
__device__ float2  g_es2[BATCH * NN];        // (2^s~, 2^{0.2 s~})
__device__ float2  g_et2[BATCH * NN];        // (2^t~, 2^{0.2 t~})

// ---------------- helpers ---------------------------------------------------
__device__ __forceinline__ float ex2f(float x) {
    float r; asm("ex2.approx.f32 %0, %1;" : "=f"(r) : "f"(x)); return r;
}
__device__ __forceinline__ void ldsm4(uint32_t& r0, uint32_t& r1, uint32_t& r2,
                                      uint32_t& r3, uint32_t a) {
    asm volatile("ldmatrix.sync.aligned.m8n8.x4.shared.b16 {%0,%1,%2,%3}, [%4];"
                 : "=r"(r0), "=r"(r1), "=r"(r2), "=r"(r3) : "r"(a));
}

// ---------------------------------------------------------------------------
// Kernel 1: X = H @ W (fp32, tiled). Emits g_X (fp32) and g_XTh (fp16, T).
// ---------------------------------------------------------------------------
__global__ void __launch_bounds__(256) xgemm_kernel(const float* __restrict__ H,
                                                    const float* __restrict__ W) {
    __shared__ float Hst[64][68];
    __shared__ float Ws[64][64];
    const int row0 = blockIdx.x * 64;
    const int t = threadIdx.x;
    const int ty = t >> 4, tx = t & 15;

    float acc[4][4];
#pragma unroll
    for (int i = 0; i < 4; ++i)
#pragma unroll
        for (int j = 0; j < 4; ++j) acc[i][j] = 0.f;

    for (int kk = 0; kk < 2; ++kk) {
#pragma unroll
        for (int q = 0; q < 4; ++q) {
            int idx = t + q * 256;
            int r = idx >> 4, c4 = idx & 15;
            float4 v = *(const float4*)(H + (size_t)(row0 + r) * FF + kk * 64 + c4 * 4);
            Hst[c4 * 4 + 0][r] = v.x;
            Hst[c4 * 4 + 1][r] = v.y;
            Hst[c4 * 4 + 2][r] = v.z;
            Hst[c4 * 4 + 3][r] = v.w;
            float4 wv = *(const float4*)(W + (size_t)(kk * 64 + r) * UU + c4 * 4);
            *(float4*)&Ws[r][c4 * 4] = wv;
        }
        __syncthreads();
#pragma unroll
        for (int k = 0; k < 64; ++k) {
            float4 a = *(float4*)&Hst[k][ty * 4];
            float4 bv = *(float4*)&Ws[k][tx * 4];
            float ar[4] = {a.x, a.y, a.z, a.w};
            float br[4] = {bv.x, bv.y, bv.z, bv.w};
#pragma unroll
            for (int i = 0; i < 4; ++i)
#pragma unroll
                for (int j = 0; j < 4; ++j) acc[i][j] += ar[i] * br[j];
        }
        __syncthreads();
    }
    const int bb = row0 >> 12;          // batch
    const int n0 = row0 & (NN - 1);
#pragma unroll
    for (int i = 0; i < 4; ++i) {
        float4 v = make_float4(acc[i][0], acc[i][1], acc[i][2], acc[i][3]);
        *(float4*)(g_X + (size_t)(row0 + ty * 4 + i) * UU + tx * 4) = v;
    }
#pragma unroll
    for (int j = 0; j < 4; ++j) {
        __half2 h01 = __floats2half2_rn(acc[0][j], acc[1][j]);
        __half2 h23 = __floats2half2_rn(acc[2][j], acc[3][j]);
        uint2 pv = make_uint2(*(uint32_t*)&h01, *(uint32_t*)&h23);
        *(uint2*)(g_XTh + ((size_t)bb * UU + tx * 4 + j) * NN + n0 + ty * 4) = pv;
    }
}

// ---------------------------------------------------------------------------
// Kernel 2: per-row exp factors. s~ = (X@a1)*log2e, t~ = (X@a2)*log2e
// ---------------------------------------------------------------------------
__global__ void __launch_bounds__(256) st_kernel(const float* __restrict__ a1,
                                                 const float* __restrict__ a2) {
    int gw = (blockIdx.x * blockDim.x + threadIdx.x) >> 5;
    int lane = threadIdx.x & 31;
    float x0 = g_X[(size_t)gw * UU + lane];
    float x1 = g_X[(size_t)gw * UU + 32 + lane];
    float sv = x0 * a1[lane] + x1 * a1[lane + 32];
    float tv = x0 * a2[lane] + x1 * a2[lane + 32];
#pragma unroll
    for (int o = 16; o; o >>= 1) {
        sv += __shfl_xor_sync(0xffffffffu, sv, o);
        tv += __shfl_xor_sync(0xffffffffu, tv, o);
    }
    if (lane == 0) {
        sv *= LOG2E; tv *= LOG2E;
        g_es2[gw] = make_float2(ex2f(sv), ex2f(0.2f * sv));
        g_et2[gw] = make_float2(ex2f(tv), ex2f(0.2f * tv));
    }
}

// ---------------------------------------------------------------------------
// Kernel 3: fused mask + softmax + P@X, double-buffered, ldmatrix fragments.
// Grid (32, 8). CTA = 256 thr (8 warps); warp w owns rows [16w, 16w+16).
// One barrier per tile: write(jt+1) into buf nxt || MMA(jt) on buf cur.
// ---------------------------------------------------------------------------
#define XWORDS (64 * XSTR)            // 2304 words per X buffer
#define PWORDS (128 * PSTR)           // 4608 words per P buffer
#define WPS0 (2 * XWORDS)             // Ps base (word offset)
#define WZS (WPS0 + 2 * PWORDS)       // Zs: [128] float
#define WES (WZS + 128)               // Es2: [128] float2
#define SMEM_GAT ((WES + 256) * 4)    // 56832 B

__global__ void __launch_bounds__(256, 2) gat_kernel(const float* __restrict__ A,
                                                     float* __restrict__ out) {
    extern __shared__ float sm[];
    uint32_t* XsW = (uint32_t*)sm;            // word-indexed, 2 buffers
    uint32_t* PsW = (uint32_t*)sm + WPS0;     // 2 buffers
    float* Zs = sm + WZS;
    float2* Es2 = (float2*)(sm + WES);
    const uint32_t smbase = (uint32_t)__cvta_generic_to_shared(sm);

    const int b = blockIdx.y;
    const int i0 = blockIdx.x * 128;
    const int tid = threadIdx.x;
    const int w = tid >> 5, lane = tid & 31;
    const int g = lane >> 2, tig = lane & 3;
    const int h = lane >> 4, c = lane & 15;
    const int wrow0 = i0 + w * 16;

    // per-lane ldmatrix byte offsets
    const uint32_t aofs = ((uint32_t)(((lane >> 3) & 1) * 8 + (lane & 7))) * (PSTR * 4)
                        + ((uint32_t)(lane >> 4)) * 16;
    const uint32_t bofs = ((uint32_t)((lane >> 4) * 8 + (lane & 7))) * (XSTR * 4)
                        + ((uint32_t)((lane >> 3) & 1)) * 16;

    // X-copy index for this thread (2 chunks)
    const int u0 = tid >> 3, ch0 = tid & 7;            // chunk 0
    const int u1 = (tid + 256) >> 3, ch1 = tid & 7;    // chunk 1

    if (tid < 128) Es2[tid] = g_es2[(size_t)b * NN + i0 + tid];

    float4 acc[8];
#pragma unroll
    for (int nb = 0; nb < 8; ++nb) acc[nb] = make_float4(0.f, 0.f, 0.f, 0.f);
    float zp[8];
#pragma unroll
    for (int it = 0; it < 8; ++it) zp[it] = 0.f;

    const float* Abase = A + ((size_t)b * NN + wrow0 + 8 * h) * NN + 4 * c;
    const float2* etb = g_et2 + (size_t)b * NN + 4 * c;
    const __half* XTb = g_XTh + (size_t)b * UU * NN;
    const float2* Esw = Es2 + w * 16 + 8 * h;

    // ---- prologue: fill buffer 0 with tile 0 ----
    float4 mv[8];
#pragma unroll
    for (int it = 0; it < 8; ++it)
        mv[it] = __ldcs((const float4*)(Abase + (size_t)it * NN));
    uint4 xv0 = *(const uint4*)(XTb + (size_t)u0 * NN + ch0 * 8);
    uint4 xv1 = *(const uint4*)(XTb + (size_t)u1 * NN + ch1 * 8);
    __syncthreads();                          // Es2 visible
    {
        float4 et01 = *(const float4*)(etb);
        float4 et23 = *(const float4*)(etb + 2);
        uint32_t* Pn = PsW;                   // buffer 0
#pragma unroll
        for (int it = 0; it < 8; ++it) {
            float4 m = mv[it];
            float2 ef = Esw[it];
            float e0 = m.x * fmaxf(ef.x * et01.x, ef.y * et01.y);
            float e1 = m.y * fmaxf(ef.x * et01.z, ef.y * et01.w);
            float e2 = m.z * fmaxf(ef.x * et23.x, ef.y * et23.y);
            float e3 = m.w * fmaxf(ef.x * et23.z, ef.y * et23.w);
            zp[it] += (e0 + e1) + (e2 + e3);
            __half2 p01 = __floats2half2_rn(e0, e1);
            __half2 p23 = __floats2half2_rn(e2, e3);
            *(uint2*)&Pn[(it + 8 * h + w * 16) * PSTR + 2 * c] =
                make_uint2(*(uint32_t*)&p01, *(uint32_t*)&p23);
        }
#pragma unroll
        for (int it = 0; it < 8; ++it)      // A for tile 1
            mv[it] = __ldcs((const float4*)(Abase + (size_t)(64 + it * NN)));
        *(uint4*)&XsW[u0 * XSTR + ch0 * 4] = xv0;
        *(uint4*)&XsW[u1 * XSTR + ch1 * 4] = xv1;
    }
    __syncthreads();                          // buffer 0 ready

    // ---- main loop ----
    for (int jt = 0; jt < 64; ++jt) {
        const int cur = jt & 1, nxt = cur ^ 1;

        if (jt < 63) {
            const int j1 = (jt + 1) * 64;
            // X loads for tile jt+1 (STS deferred past MMA)
            xv0 = *(const uint4*)(XTb + (size_t)u0 * NN + j1 + ch0 * 8);
            xv1 = *(const uint4*)(XTb + (size_t)u1 * NN + j1 + ch1 * 8);
            // P stage for tile jt+1 (consumes mv = A(jt+1))
            float4 et01 = *(const float4*)(etb + j1);
            float4 et23 = *(const float4*)(etb + j1 + 2);
            uint32_t* Pn = PsW + nxt * PWORDS;
#pragma unroll
            for (int it = 0; it < 8; ++it) {
                float4 m = mv[it];
                float2 ef = Esw[it];
                float e0 = m.x * fmaxf(ef.x * et01.x, ef.y * et01.y);
                float e1 = m.y * fmaxf(ef.x * et01.z, ef.y * et01.w);
                float e2 = m.z * fmaxf(ef.x * et23.x, ef.y * et23.y);
                float e3 = m.w * fmaxf(ef.x * et23.z, ef.y * et23.w);
                zp[it] += (e0 + e1) + (e2 + e3);
                __half2 p01 = __floats2half2_rn(e0, e1);
                __half2 p23 = __floats2half2_rn(e2, e3);
                *(uint2*)&Pn[(it + 8 * h + w * 16) * PSTR + 2 * c] =
                    make_uint2(*(uint32_t*)&p01, *(uint32_t*)&p23);
            }
            // A prefetch for tile jt+2 (drains during MMA)
            const float* Apn = Abase + (size_t)(((jt + 2) & 63) * 64);
#pragma unroll
            for (int it = 0; it < 8; ++it)
                mv[it] = __ldcs((const float4*)(Apn + (size_t)it * NN));
        }

        // --- MMA(jt) on buffer cur: ldmatrix fragments ---
        {
            const uint32_t pa = smbase + (WPS0 + cur * PWORDS + w * 16 * PSTR) * 4 + aofs;
            const uint32_t pb = smbase + (cur * XWORDS) * 4 + bofs;
#pragma unroll
            for (int kc = 0; kc < 4; ++kc) {
                uint32_t a0, a1, a2v, a3;
                ldsm4(a0, a1, a2v, a3, pa + kc * 32);
#pragma unroll
                for (int pr = 0; pr < 4; ++pr) {
                    uint32_t b0, b1, b2, b3;
                    ldsm4(b0, b1, b2, b3, pb + pr * (16 * XSTR * 4) + kc * 32);
                    asm volatile(
                        "mma.sync.aligned.m16n8k16.row.col.f32.f16.f16.f32 "
                        "{%0,%1,%2,%3}, {%4,%5,%6,%7}, {%8,%9}, {%0,%1,%2,%3};\n"
                        : "+f"(acc[2 * pr].x), "+f"(acc[2 * pr].y),
                          "+f"(acc[2 * pr].z), "+f"(acc[2 * pr].w)
                        : "r"(a0), "r"(a1), "r"(a2v), "r"(a3), "r"(b0), "r"(b1));
                    asm volatile(
                        "mma.sync.aligned.m16n8k16.row.col.f32.f16.f16.f32 "
                        "{%0,%1,%2,%3}, {%4,%5,%6,%7}, {%8,%9}, {%0,%1,%2,%3};\n"
                        : "+f"(acc[2 * pr + 1].x), "+f"(acc[2 * pr + 1].y),
                          "+f"(acc[2 * pr + 1].z), "+f"(acc[2 * pr + 1].w)
                        : "r"(a0), "r"(a1), "r"(a2v), "r"(a3), "r"(b2), "r"(b3));
                }
            }
        }

        if (jt < 63) {   // deferred X stores (data arrived during MMA)
            uint32_t* Xn = XsW + nxt * XWORDS;
            *(uint4*)&Xn[u0 * XSTR + ch0 * 4] = xv0;
            *(uint4*)&Xn[u1 * XSTR + ch1 * 4] = xv1;
        }
        __syncthreads();   // buf nxt complete; MMA readers of cur done
    }

    // --- Z reduction: rows it (lanes 0-15) and it+8 (lanes 16-31) ---
#pragma unroll
    for (int it = 0; it < 8; ++it) {
        float v = zp[it];
#pragma unroll
        for (int o = 8; o; o >>= 1) v += __shfl_xor_sync(0xffffffffu, v, o);
        if (c == 0) Zs[w * 16 + 8 * h + it] = v;
    }
    __syncwarp();

    // --- epilogue: relu(D / Z) ---
    float inv0 = 1.0f / Zs[w * 16 + g];
    float inv1 = 1.0f / Zs[w * 16 + g + 8];
    float* outb = out + ((size_t)b * NN + wrow0) * UU;
#pragma unroll
    for (int nb = 0; nb < 8; ++nb) {
        int col = nb * 8 + tig * 2;
        float2 v0 = make_float2(fmaxf(acc[nb].x * inv0, 0.f), fmaxf(acc[nb].y * inv0, 0.f));
        float2 v1 = make_float2(fmaxf(acc[nb].z * inv1, 0.f), fmaxf(acc[nb].w * inv1, 0.f));
        *(float2*)(outb + (size_t)g * UU + col) = v0;
        *(float2*)(outb + (size_t)(g + 8) * UU + col) = v1;
    }
}

// ---------------------------------------------------------------------------
extern "C" void kernel_launch(void* const* d_in, const int* in_sizes, int n_in,
                              void* d_out, int out_size) {
    const float* H = (const float*)d_in[0];       // [8,4096,128]
    const float* Amask = (const float*)d_in[1];   // [8,4096,4096]
    const float* W = (const float*)d_in[2];       // [128,64]
    const float* a1 = (const float*)d_in[3];      // [64,1]
    const float* a2 = (const float*)d_in[4];      // [64,1]
    float* out = (float*)d_out;                   // [8,4096,64]

    cudaFuncSetAttribute(gat_kernel, cudaFuncAttributeMaxDynamicSharedMemorySize, SMEM_GAT);

    xgemm_kernel<<<(BATCH * NN) / 64, 256>>>(H, W);
    st_kernel<<<(BATCH * NN) / 8, 256>>>(a1, a2);
    gat_kernel<<<dim3(NN / 128, BATCH), 256, SMEM_GAT>>>(Amask, out);
}

// round 15
// speedup vs baseline: 3.5779x; 1.0797x over previous
#include <cuda_runtime.h>
#include <cuda_fp16.h>
#include <cstdint>

#define BATCH 8
#define NN 4096
#define FF 128
#define UU 64
#define LOG2E 1.4426950408889634f
#define XSTR 36   // gat: Xs row stride in half2 words
#define PSTR 36   // gat: Ps row stride in half2 words

// ---------------- device scratch (no allocations allowed) -------------------
__device__ __half  g_XTh[BATCH * UU * NN];   // X^T per batch, fp16
__device__ float2  g_es2[BATCH * NN];        // (2^s~, 2^{0.2 s~})
__device__ float2  g_et2[BATCH * NN];        // (2^t~, 2^{0.2 t~})
__device__ float2  g_w12[FF];                // (W@a1, W@a2) per k

// ---------------- helpers ---------------------------------------------------
__device__ __forceinline__ float ex2f(float x) {
    float r; asm("ex2.approx.f32 %0, %1;" : "=f"(r) : "f"(x)); return r;
}
__device__ __forceinline__ void ldsm4(uint32_t& r0, uint32_t& r1, uint32_t& r2,
                                      uint32_t& r3, uint32_t a) {
    asm volatile("ldmatrix.sync.aligned.m8n8.x4.shared.b16 {%0,%1,%2,%3}, [%4];"
                 : "=r"(r0), "=r"(r1), "=r"(r2), "=r"(r3) : "r"(a));
}
__device__ __forceinline__ uint32_t packh2(float a, float b) {
    __half2 h = __floats2half2_rn(a, b);
    return *(uint32_t*)&h;
}

// ---------------------------------------------------------------------------
// Kernel 0: w1 = W@a1, w2 = W@a2  (one CTA, 128 threads)
// ---------------------------------------------------------------------------
__global__ void wk_kernel(const float* __restrict__ W, const float* __restrict__ a1,
                          const float* __restrict__ a2) {
    int k = threadIdx.x;
    float s1 = 0.f, s2 = 0.f;
#pragma unroll 16
    for (int u = 0; u < UU; ++u) {
        float wv = W[k * UU + u];
        s1 += wv * a1[u];
        s2 += wv * a2[u];
    }
    g_w12[k] = make_float2(s1, s2);
}

// ---------------------------------------------------------------------------
// Kernel 1: s~,t~ from fp32 H directly: s = H@w1 (full precision path).
// Warp handles 8 rows. Grid 512 x 256.
// ---------------------------------------------------------------------------
__global__ void __launch_bounds__(256) st2_kernel(const float* __restrict__ H) {
    const int w = threadIdx.x >> 5, lane = threadIdx.x & 31;
    const int gw = blockIdx.x * 8 + w;       // 0..4095, rows gw*8..gw*8+7
    float2 w0 = g_w12[lane], w1v = g_w12[lane + 32];
    float2 w2v = g_w12[lane + 64], w3 = g_w12[lane + 96];
#pragma unroll
    for (int i = 0; i < 8; ++i) {
        const int row = gw * 8 + i;
        const float* Hp = H + (size_t)row * FF;
        float h0 = Hp[lane], h1 = Hp[lane + 32], h2 = Hp[lane + 64], h3 = Hp[lane + 96];
        float sv = h0 * w0.x + h1 * w1v.x + h2 * w2v.x + h3 * w3.x;
        float tv = h0 * w0.y + h1 * w1v.y + h2 * w2v.y + h3 * w3.y;
#pragma unroll
        for (int o = 16; o; o >>= 1) {
            sv += __shfl_xor_sync(0xffffffffu, sv, o);
            tv += __shfl_xor_sync(0xffffffffu, tv, o);
        }
        if (lane == 0) {
            sv *= LOG2E; tv *= LOG2E;
            g_es2[row] = make_float2(ex2f(sv), ex2f(0.2f * sv));
            g_et2[row] = make_float2(ex2f(tv), ex2f(0.2f * tv));
        }
    }
}

// ---------------------------------------------------------------------------
// Kernel 2: X^T (fp16) = (H @ W)^T via m16n8k16 MMA. 256 CTAs x 256 thr.
// CTA: 128 rows x 64 U-cols, K=128. smem: Hh[128][136h] + Wt[64][136h];
// epilogue stages X^T[64][128+pad] fp16 in smem (reusing Hh) for coalesced out.
// ---------------------------------------------------------------------------
#define XG_HW 68                       // row stride in words (136 halves)
#define XG_WT (128 * XG_HW)            // Wt word base
#define XG_SMEM ((XG_WT + 64 * XG_HW) * 4)   // 52224 B

__global__ void __launch_bounds__(256) xgemm16_kernel(const float* __restrict__ H,
                                                      const float* __restrict__ W) {
    extern __shared__ uint32_t smw[];
    __half* Wth = (__half*)(smw + XG_WT);
    const uint32_t smbase = (uint32_t)__cvta_generic_to_shared(smw);

    const int row0 = blockIdx.x * 128;
    const int t = threadIdx.x;
    const int w = t >> 5, lane = t & 31;
    const int g = lane >> 2, tig = lane & 3;
    const int m0 = w * 16;

    // --- load H tile -> fp16 smem [r][k], stride 68 words ---
#pragma unroll
    for (int q = 0; q < 16; ++q) {
        int idx = t + q * 256;
        int r = idx >> 5, c4 = idx & 31;
        float4 v = *(const float4*)(H + (size_t)(row0 + r) * FF + c4 * 4);
        *(uint2*)&smw[r * XG_HW + c4 * 2] = make_uint2(packh2(v.x, v.y), packh2(v.z, v.w));
    }
    // --- load W -> transposed fp16 smem Wt[u][k] ---
#pragma unroll
    for (int q = 0; q < 32; ++q) {
        int idx = t + q * 256;
        int k = idx >> 6, u = idx & 63;
        Wth[u * 136 + k] = __float2half_rn(W[idx]);
    }
    __syncthreads();

    // --- MMA: X[128x64] = H[128x128] @ W (b from Wt rows = u) ---
    float4 acc[8];
#pragma unroll
    for (int nb = 0; nb < 8; ++nb) acc[nb] = make_float4(0.f, 0.f, 0.f, 0.f);

    const uint32_t aofs = ((uint32_t)(((lane >> 3) & 1) * 8 + (lane & 7))) * 272
                        + ((uint32_t)(lane >> 4)) * 16;
    const uint32_t bofs = ((uint32_t)((lane >> 4) * 8 + (lane & 7))) * 272
                        + ((uint32_t)((lane >> 3) & 1)) * 16;
    const uint32_t pa = smbase + m0 * 272 + aofs;
    const uint32_t pb = smbase + XG_WT * 4 + bofs;

#pragma unroll
    for (int kc = 0; kc < 8; ++kc) {
        uint32_t a0, a1, a2v, a3;
        ldsm4(a0, a1, a2v, a3, pa + kc * 32);
#pragma unroll
        for (int pr = 0; pr < 4; ++pr) {
            uint32_t b0, b1, b2, b3;
            ldsm4(b0, b1, b2, b3, pb + pr * (16 * 272) + kc * 32);
            asm volatile(
                "mma.sync.aligned.m16n8k16.row.col.f32.f16.f16.f32 "
                "{%0,%1,%2,%3}, {%4,%5,%6,%7}, {%8,%9}, {%0,%1,%2,%3};\n"
                : "+f"(acc[2 * pr].x), "+f"(acc[2 * pr].y),
                  "+f"(acc[2 * pr].z), "+f"(acc[2 * pr].w)
                : "r"(a0), "r"(a1), "r"(a2v), "r"(a3), "r"(b0), "r"(b1));
            asm volatile(
                "mma.sync.aligned.m16n8k16.row.col.f32.f16.f16.f32 "
                "{%0,%1,%2,%3}, {%4,%5,%6,%7}, {%8,%9}, {%0,%1,%2,%3};\n"
                : "+f"(acc[2 * pr + 1].x), "+f"(acc[2 * pr + 1].y),
                  "+f"(acc[2 * pr + 1].z), "+f"(acc[2 * pr + 1].w)
                : "r"(a0), "r"(a1), "r"(a2v), "r"(a3), "r"(b2), "r"(b3));
        }
    }
    __syncthreads();   // all warps done reading Hh before reuse

    // --- stage X^T fp16 in smem (reuse Hh region): Xsm[u][m], stride 136 ---
    __half* Xsm = (__half*)smw;
#pragma unroll
    for (int nb = 0; nb < 8; ++nb) {
        int n = nb * 8 + tig * 2;
        Xsm[n * 136 + m0 + g] = __float2half_rn(acc[nb].x);
        Xsm[(n + 1) * 136 + m0 + g] = __float2half_rn(acc[nb].y);
        Xsm[n * 136 + m0 + g + 8] = __float2half_rn(acc[nb].z);
        Xsm[(n + 1) * 136 + m0 + g + 8] = __float2half_rn(acc[nb].w);
    }
    __syncthreads();

    // --- coalesced copy out: g_XTh[bb*64+u][n0 + 0..127] ---
    // 64 rows x 128 halves = 8192 halves = 1024 uint4 chunks -> q < 4.
    const int bb = row0 >> 12, n0 = row0 & (NN - 1);
#pragma unroll
    for (int q = 0; q < 4; ++q) {
        int idx = t + q * 256;
        int u = idx >> 4, ch = idx & 15;
        uint4 v = *(uint4*)&smw[u * XG_HW + ch * 4];
        *(uint4*)(g_XTh + ((size_t)bb * UU + u) * NN + n0 + ch * 8) = v;
    }
}

// ---------------------------------------------------------------------------
// Kernel 3: fused mask + softmax + P@X (identical to R10 passing version).
// ---------------------------------------------------------------------------
#define XWORDS (64 * XSTR)
#define PWORDS (128 * PSTR)
#define WPS0 (2 * XWORDS)
#define WZS (WPS0 + 2 * PWORDS)
#define WES (WZS + 128)
#define SMEM_GAT ((WES + 256) * 4)

__global__ void __launch_bounds__(256, 2) gat_kernel(const float* __restrict__ A,
                                                     float* __restrict__ out) {
    extern __shared__ float sm[];
    uint32_t* XsW = (uint32_t*)sm;
    uint32_t* PsW = (uint32_t*)sm + WPS0;
    float* Zs = sm + WZS;
    float2* Es2 = (float2*)(sm + WES);
    const uint32_t smbase = (uint32_t)__cvta_generic_to_shared(sm);

    const int b = blockIdx.y;
    const int i0 = blockIdx.x * 128;
    const int tid = threadIdx.x;
    const int w = tid >> 5, lane = tid & 31;
    const int g = lane >> 2, tig = lane & 3;
    const int h = lane >> 4, c = lane & 15;
    const int wrow0 = i0 + w * 16;

    const uint32_t aofs = ((uint32_t)(((lane >> 3) & 1) * 8 + (lane & 7))) * (PSTR * 4)
                        + ((uint32_t)(lane >> 4)) * 16;
    const uint32_t bofs = ((uint32_t)((lane >> 4) * 8 + (lane & 7))) * (XSTR * 4)
                        + ((uint32_t)((lane >> 3) & 1)) * 16;

    const int u0 = tid >> 3, ch0 = tid & 7;
    const int u1 = (tid + 256) >> 3, ch1 = tid & 7;

    if (tid < 128) Es2[tid] = g_es2[(size_t)b * NN + i0 + tid];

    float4 acc[8];
#pragma unroll
    for (int nb = 0; nb < 8; ++nb) acc[nb] = make_float4(0.f, 0.f, 0.f, 0.f);
    float zp[8];
#pragma unroll
    for (int it = 0; it < 8; ++it) zp[it] = 0.f;

    const float* Abase = A + ((size_t)b * NN + wrow0 + 8 * h) * NN + 4 * c;
    const float2* etb = g_et2 + (size_t)b * NN + 4 * c;
    const __half* XTb = g_XTh + (size_t)b * UU * NN;
    const float2* Esw = Es2 + w * 16 + 8 * h;

    float4 mv[8];
#pragma unroll
    for (int it = 0; it < 8; ++it)
        mv[it] = __ldcs((const float4*)(Abase + (size_t)it * NN));
    uint4 xv0 = *(const uint4*)(XTb + (size_t)u0 * NN + ch0 * 8);
    uint4 xv1 = *(const uint4*)(XTb + (size_t)u1 * NN + ch1 * 8);
    __syncthreads();
    {
        float4 et01 = *(const float4*)(etb);
        float4 et23 = *(const float4*)(etb + 2);
        uint32_t* Pn = PsW;
#pragma unroll
        for (int it = 0; it < 8; ++it) {
            float4 m = mv[it];
            float2 ef = Esw[it];
            float e0 = m.x * fmaxf(ef.x * et01.x, ef.y * et01.y);
            float e1 = m.y * fmaxf(ef.x * et01.z, ef.y * et01.w);
            float e2 = m.z * fmaxf(ef.x * et23.x, ef.y * et23.y);
            float e3 = m.w * fmaxf(ef.x * et23.z, ef.y * et23.w);
            zp[it] += (e0 + e1) + (e2 + e3);
            *(uint2*)&Pn[(it + 8 * h + w * 16) * PSTR + 2 * c] =
                make_uint2(packh2(e0, e1), packh2(e2, e3));
        }
#pragma unroll
        for (int it = 0; it < 8; ++it)
            mv[it] = __ldcs((const float4*)(Abase + (size_t)(64 + it * NN)));
        *(uint4*)&XsW[u0 * XSTR + ch0 * 4] = xv0;
        *(uint4*)&XsW[u1 * XSTR + ch1 * 4] = xv1;
    }
    __syncthreads();

    for (int jt = 0; jt < 64; ++jt) {
        const int cur = jt & 1, nxt = cur ^ 1;

        if (jt < 63) {
            const int j1 = (jt + 1) * 64;
            xv0 = *(const uint4*)(XTb + (size_t)u0 * NN + j1 + ch0 * 8);
            xv1 = *(const uint4*)(XTb + (size_t)u1 * NN + j1 + ch1 * 8);
            float4 et01 = *(const float4*)(etb + j1);
            float4 et23 = *(const float4*)(etb + j1 + 2);
            uint32_t* Pn = PsW + nxt * PWORDS;
#pragma unroll
            for (int it = 0; it < 8; ++it) {
                float4 m = mv[it];
                float2 ef = Esw[it];
                float e0 = m.x * fmaxf(ef.x * et01.x, ef.y * et01.y);
                float e1 = m.y * fmaxf(ef.x * et01.z, ef.y * et01.w);
                float e2 = m.z * fmaxf(ef.x * et23.x, ef.y * et23.y);
                float e3 = m.w * fmaxf(ef.x * et23.z, ef.y * et23.w);
                zp[it] += (e0 + e1) + (e2 + e3);
                *(uint2*)&Pn[(it + 8 * h + w * 16) * PSTR + 2 * c] =
                    make_uint2(packh2(e0, e1), packh2(e2, e3));
            }
            const float* Apn = Abase + (size_t)(((jt + 2) & 63) * 64);
#pragma unroll
            for (int it = 0; it < 8; ++it)
                mv[it] = __ldcs((const float4*)(Apn + (size_t)it * NN));
        }

        {
            const uint32_t pa = smbase + (WPS0 + cur * PWORDS + w * 16 * PSTR) * 4 + aofs;
            const uint32_t pb = smbase + (cur * XWORDS) * 4 + bofs;
#pragma unroll
            for (int kc = 0; kc < 4; ++kc) {
                uint32_t a0, a1, a2v, a3;
                ldsm4(a0, a1, a2v, a3, pa + kc * 32);
#pragma unroll
                for (int pr = 0; pr < 4; ++pr) {
                    uint32_t b0, b1, b2, b3;
                    ldsm4(b0, b1, b2, b3, pb + pr * (16 * XSTR * 4) + kc * 32);
                    asm volatile(
                        "mma.sync.aligned.m16n8k16.row.col.f32.f16.f16.f32 "
                        "{%0,%1,%2,%3}, {%4,%5,%6,%7}, {%8,%9}, {%0,%1,%2,%3};\n"
                        : "+f"(acc[2 * pr].x), "+f"(acc[2 * pr].y),
                          "+f"(acc[2 * pr].z), "+f"(acc[2 * pr].w)
                        : "r"(a0), "r"(a1), "r"(a2v), "r"(a3), "r"(b0), "r"(b1));
                    asm volatile(
                        "mma.sync.aligned.m16n8k16.row.col.f32.f16.f16.f32 "
                        "{%0,%1,%2,%3}, {%4,%5,%6,%7}, {%8,%9}, {%0,%1,%2,%3};\n"
                        : "+f"(acc[2 * pr + 1].x), "+f"(acc[2 * pr + 1].y),
                          "+f"(acc[2 * pr + 1].z), "+f"(acc[2 * pr + 1].w)
                        : "r"(a0), "r"(a1), "r"(a2v), "r"(a3), "r"(b2), "r"(b3));
                }
            }
        }

        if (jt < 63) {
            uint32_t* Xn = XsW + nxt * XWORDS;
            *(uint4*)&Xn[u0 * XSTR + ch0 * 4] = xv0;
            *(uint4*)&Xn[u1 * XSTR + ch1 * 4] = xv1;
        }
        __syncthreads();
    }

#pragma unroll
    for (int it = 0; it < 8; ++it) {
        float v = zp[it];
#pragma unroll
        for (int o = 8; o; o >>= 1) v += __shfl_xor_sync(0xffffffffu, v, o);
        if (c == 0) Zs[w * 16 + 8 * h + it] = v;
    }
    __syncwarp();

    float inv0 = 1.0f / Zs[w * 16 + g];
    float inv1 = 1.0f / Zs[w * 16 + g + 8];
    float* outb = out + ((size_t)b * NN + wrow0) * UU;
#pragma unroll
    for (int nb = 0; nb < 8; ++nb) {
        int col = nb * 8 + tig * 2;
        float2 v0 = make_float2(fmaxf(acc[nb].x * inv0, 0.f), fmaxf(acc[nb].y * inv0, 0.f));
        float2 v1 = make_float2(fmaxf(acc[nb].z * inv1, 0.f), fmaxf(acc[nb].w * inv1, 0.f));
        *(float2*)(outb + (size_t)g * UU + col) = v0;
        *(float2*)(outb + (size_t)(g + 8) * UU + col) = v1;
    }
}

// ---------------------------------------------------------------------------
extern "C" void kernel_launch(void* const* d_in, const int* in_sizes, int n_in,
                              void* d_out, int out_size) {
    const float* H = (const float*)d_in[0];       // [8,4096,128]
    const float* Amask = (const float*)d_in[1];   // [8,4096,4096]
    const float* W = (const float*)d_in[2];       // [128,64]
    const float* a1 = (const float*)d_in[3];      // [64,1]
    const float* a2 = (const float*)d_in[4];      // [64,1]
    float* out = (float*)d_out;                   // [8,4096,64]

    cudaFuncSetAttribute(xgemm16_kernel, cudaFuncAttributeMaxDynamicSharedMemorySize, XG_SMEM);
    cudaFuncSetAttribute(gat_kernel, cudaFuncAttributeMaxDynamicSharedMemorySize, SMEM_GAT);

    wk_kernel<<<1, 128>>>(W, a1, a2);
    st2_kernel<<<512, 256>>>(H);
    xgemm16_kernel<<<(BATCH * NN) / 128, 256, XG_SMEM>>>(H, W);
    gat_kernel<<<dim3(NN / 128, BATCH), 256, SMEM_GAT>>>(Amask, out);
}